// round 6
// baseline (speedup 1.0000x reference)
#include <cuda_runtime.h>

#define BB 4
#define TT 2048
#define CC 1024
#define HS 64
#define KSPLIT 8
#define SCALE 0.03125f   // C^-0.5 = 1024^-0.5

typedef unsigned long long u64;

// ---- packed f32x2 helpers (sm_100+ PTX) -----------------------------------
__device__ __forceinline__ u64 pk1(float x) {
    u64 r; asm("mov.b64 %0,{%1,%1};" : "=l"(r) : "f"(x)); return r;
}
__device__ __forceinline__ void fma2(u64& d, u64 a, u64 b) {
    asm("fma.rn.f32x2 %0,%1,%2,%0;" : "+l"(d) : "l"(a), "l"(b));
}
__device__ __forceinline__ void mul2(u64& d, u64 a) {
    asm("mul.rn.f32x2 %0,%0,%1;" : "+l"(d) : "l"(a));
}
__device__ __forceinline__ void upk(u64 v, float& lo, float& hi) {
    asm("mov.b64 {%0,%1},%2;" : "=f"(lo), "=f"(hi) : "l"(v));
}
__device__ __forceinline__ u64 swp(u64 v) {
    u64 r;
    asm("{\n\t.reg .b32 lo,hi;\n\tmov.b64 {lo,hi},%1;\n\tmov.b64 %0,{hi,lo};\n\t}"
        : "=l"(r) : "l"(v));
    return r;
}

// Scratch (static device allocations; no cudaMalloc allowed)
__device__ float g_q[BB * TT * HS];
__device__ float g_k[BB * TT * HS];
__device__ float g_v[BB * TT * HS];
__device__ float g_p2[3 * BB * TT * HS];    // K-split second-half partials
__device__ float g_pacc[(size_t)BB * KSPLIT * TT * HS];
__device__ float g_pm[BB * KSPLIT * TT];
__device__ float g_pl[BB * KSPLIT * TT];

// ---------------------------------------------------------------------------
// Kernel 1: QKV projection with K-split.  Diagonal/cross FFMA2 micro-kernel:
// per kk only 2 LDS.128 + 2 swaps + 8 FFMA2 (no operand-packing movs).
// grid = (128 row-tiles, 3 matrices, 2 k-halves), 256 threads, BM=BN=64, BK=32.
// ---------------------------------------------------------------------------
__global__ __launch_bounds__(256) void qkv_kernel(
    const float* __restrict__ x,
    const float* __restrict__ Wq,
    const float* __restrict__ Wk,
    const float* __restrict__ Wv) {
    const int m = blockIdx.y;
    const float* W = (m == 0) ? Wq : (m == 1) ? Wk : Wv;
    float* out = (blockIdx.z == 0)
        ? ((m == 0) ? g_q : (m == 1) ? g_k : g_v)
        : &g_p2[(size_t)m * BB * TT * HS];

    __shared__ float Xs[32][68];   // [k][row], padded stride (16B aligned)
    __shared__ float Ws[32][64];   // [k][col]

    const int tid = threadIdx.x;
    const int tx = tid & 15;       // col group (4 cols at tx*4)
    const int ty = tid >> 4;       // row group (4 rows at ty*4)
    const int row0 = blockIdx.x * 64;
    const int kbase = blockIdx.z * (CC / 2);

    const int lrow = tid >> 2;     // 0..63  X loader row
    const int lq   = tid & 3;      // 0..3
    const int wk   = tid >> 3;     // 0..31  W loader k
    const int wf   = tid & 7;      // 0..7

    // diag/cross accumulators: [row-pair p][col-pair q]
    u64 aD[2][2] = {}, aX[2][2] = {};

    float4 px0, px1, pw0, pw1;
    {   // prefetch chunk 0
        const int k0 = kbase;
        px0 = *reinterpret_cast<const float4*>(
            &x[(size_t)(row0 + lrow) * CC + k0 + lq * 4]);
        px1 = *reinterpret_cast<const float4*>(
            &x[(size_t)(row0 + lrow) * CC + k0 + (lq + 4) * 4]);
        pw0 = *reinterpret_cast<const float4*>(&W[(size_t)(k0 + wk) * HS + wf * 4]);
        pw1 = *reinterpret_cast<const float4*>(&W[(size_t)(k0 + wk) * HS + (wf + 8) * 4]);
    }

    for (int c = 0; c < 16; c++) {
        // store prefetched chunk
        {
            int f0 = lq, f1 = lq + 4;
            Xs[f0 * 4 + 0][lrow] = px0.x;
            Xs[f0 * 4 + 1][lrow] = px0.y;
            Xs[f0 * 4 + 2][lrow] = px0.z;
            Xs[f0 * 4 + 3][lrow] = px0.w;
            Xs[f1 * 4 + 0][lrow] = px1.x;
            Xs[f1 * 4 + 1][lrow] = px1.y;
            Xs[f1 * 4 + 2][lrow] = px1.z;
            Xs[f1 * 4 + 3][lrow] = px1.w;
            *reinterpret_cast<float4*>(&Ws[wk][wf * 4]) = pw0;
            *reinterpret_cast<float4*>(&Ws[wk][(wf + 8) * 4]) = pw1;
        }
        __syncthreads();

        // prefetch next chunk (overlaps FMA loop)
        if (c < 15) {
            const int k0 = kbase + (c + 1) * 32;
            px0 = *reinterpret_cast<const float4*>(
                &x[(size_t)(row0 + lrow) * CC + k0 + lq * 4]);
            px1 = *reinterpret_cast<const float4*>(
                &x[(size_t)(row0 + lrow) * CC + k0 + (lq + 4) * 4]);
            pw0 = *reinterpret_cast<const float4*>(
                &W[(size_t)(k0 + wk) * HS + wf * 4]);
            pw1 = *reinterpret_cast<const float4*>(
                &W[(size_t)(k0 + wk) * HS + (wf + 8) * 4]);
        }

#pragma unroll
        for (int kk = 0; kk < 32; kk++) {
            ulonglong2 av = *reinterpret_cast<ulonglong2*>(&Xs[kk][ty * 4]);
            ulonglong2 bv = *reinterpret_cast<ulonglong2*>(&Ws[kk][tx * 4]);
            u64 s0 = swp(bv.x), s1 = swp(bv.y);
            fma2(aD[0][0], av.x, bv.x); fma2(aD[0][1], av.x, bv.y);
            fma2(aX[0][0], av.x, s0);   fma2(aX[0][1], av.x, s1);
            fma2(aD[1][0], av.y, bv.x); fma2(aD[1][1], av.y, bv.y);
            fma2(aX[1][0], av.y, s0);   fma2(aX[1][1], av.y, s1);
        }
        __syncthreads();
    }

    // deinterleave diag/cross -> o[4][4], then store
    float o[4][4];
#pragma unroll
    for (int p = 0; p < 2; p++)
#pragma unroll
        for (int q = 0; q < 2; q++) {
            float dlo, dhi, xlo, xhi;
            upk(aD[p][q], dlo, dhi);
            upk(aX[p][q], xlo, xhi);
            o[2 * p][2 * q]         = dlo;
            o[2 * p + 1][2 * q + 1] = dhi;
            o[2 * p][2 * q + 1]     = xlo;
            o[2 * p + 1][2 * q]     = xhi;
        }
#pragma unroll
    for (int i = 0; i < 4; i++) {
        *reinterpret_cast<float4*>(
            &out[(size_t)(row0 + ty * 4 + i) * HS + tx * 4]) =
            make_float4(o[i][0], o[i][1], o[i][2], o[i][3]);
    }
}

// ---------------------------------------------------------------------------
// Kernel 1b: merge the two K-halves
// ---------------------------------------------------------------------------
__global__ __launch_bounds__(256) void qkv_add_kernel() {
    const int f4 = blockIdx.x * 256 + threadIdx.x;
    const int per = (BB * TT * HS) / 4;
    const int m = f4 / per;
    const int i = f4 - m * per;
    float* g = (m == 0) ? g_q : (m == 1) ? g_k : g_v;
    float4 a = *reinterpret_cast<float4*>(&g[i * 4]);
    float4 b = *reinterpret_cast<const float4*>(
        &g_p2[(size_t)m * BB * TT * HS + i * 4]);
    a.x += b.x; a.y += b.y; a.z += b.z; a.w += b.w;
    *reinterpret_cast<float4*>(&g[i * 4]) = a;
}

// ---------------------------------------------------------------------------
// Kernel 2: flash-attention partials.  S-loop in diag/cross form; PV loads
// V pairs directly as u64 (no packing movs).
// grid = (32 q-tiles, KSPLIT, 4 batches), 128 threads, BM=BN=64.
// ---------------------------------------------------------------------------
__global__ __launch_bounds__(128) void attn_partial_kernel() {
    const int qtile = blockIdx.x;
    const int split = blockIdx.y;
    const int b     = blockIdx.z;

    const int tid = threadIdx.x;
    const int tx = tid & 15;       // key/dim group (4 at tx*4)
    const int ty = tid >> 4;       // row group (8 at ty*8)
    const int r0 = ty * 8;
    const int c0 = tx * 4;

    __shared__ float Qt[64][64];   // [h][row], pre-scaled
    __shared__ float KP[64][64];   // K: [h][key]; reused as P: [row][key]
    __shared__ float Vs[64][64];   // [key][dim]

    const int q0 = qtile * 64;
    const int lrow = tid >> 1;
    const int lh   = tid & 1;

#pragma unroll
    for (int i = 0; i < 8; i++) {
        int f = lh + 2 * i;
        float4 qv = *reinterpret_cast<const float4*>(
            &g_q[(size_t)(b * TT + q0 + lrow) * HS + f * 4]);
        Qt[f * 4 + 0][lrow] = qv.x * SCALE;
        Qt[f * 4 + 1][lrow] = qv.y * SCALE;
        Qt[f * 4 + 2][lrow] = qv.z * SCALE;
        Qt[f * 4 + 3][lrow] = qv.w * SCALE;
    }

    float m_[8], l_[8];
    u64 acc[8][2] = {};            // 8 rows x (2 f32x2 = 4 dims)
#pragma unroll
    for (int i = 0; i < 8; i++) { m_[i] = -1e30f; l_[i] = 0.f; }

    for (int kt = split; kt <= qtile; kt += KSPLIT) {
        const int k0 = kt * 64;
        __syncthreads();

#pragma unroll
        for (int i = 0; i < 8; i++) {
            int f = lh + 2 * i;
            float4 kv = *reinterpret_cast<const float4*>(
                &g_k[(size_t)(b * TT + k0 + lrow) * HS + f * 4]);
            KP[f * 4 + 0][lrow] = kv.x;
            KP[f * 4 + 1][lrow] = kv.y;
            KP[f * 4 + 2][lrow] = kv.z;
            KP[f * 4 + 3][lrow] = kv.w;
            *reinterpret_cast<float4*>(&Vs[lrow][f * 4]) =
                *reinterpret_cast<const float4*>(
                    &g_v[(size_t)(b * TT + k0 + lrow) * HS + f * 4]);
        }
        __syncthreads();

        // ---- S = (Q*scale) K^T in diag/cross form ----
        // sD[rp][q].lo = S[2rp][2q],   sD[rp][q].hi = S[2rp+1][2q+1]
        // sX[rp][q].lo = S[2rp][2q+1], sX[rp][q].hi = S[2rp+1][2q]
        u64 sD[4][2] = {}, sX[4][2] = {};
#pragma unroll 16
        for (int h = 0; h < 64; h++) {
            ulonglong2 aA = *reinterpret_cast<ulonglong2*>(&Qt[h][r0]);
            ulonglong2 aB = *reinterpret_cast<ulonglong2*>(&Qt[h][r0 + 4]);
            ulonglong2 bV = *reinterpret_cast<ulonglong2*>(&KP[h][c0]);
            u64 s0 = swp(bV.x), s1 = swp(bV.y);
            fma2(sD[0][0], aA.x, bV.x); fma2(sD[0][1], aA.x, bV.y);
            fma2(sX[0][0], aA.x, s0);   fma2(sX[0][1], aA.x, s1);
            fma2(sD[1][0], aA.y, bV.x); fma2(sD[1][1], aA.y, bV.y);
            fma2(sX[1][0], aA.y, s0);   fma2(sX[1][1], aA.y, s1);
            fma2(sD[2][0], aB.x, bV.x); fma2(sD[2][1], aB.x, bV.y);
            fma2(sX[2][0], aB.x, s0);   fma2(sX[2][1], aB.x, s1);
            fma2(sD[3][0], aB.y, bV.x); fma2(sD[3][1], aB.y, bV.y);
            fma2(sX[3][0], aB.y, s0);   fma2(sX[3][1], aB.y, s1);
        }

        // deinterleave scores
        float s[8][4];
#pragma unroll
        for (int rp = 0; rp < 4; rp++)
#pragma unroll
            for (int q = 0; q < 2; q++) {
                float dlo, dhi, xlo, xhi;
                upk(sD[rp][q], dlo, dhi);
                upk(sX[rp][q], xlo, xhi);
                s[2 * rp][2 * q]         = dlo;
                s[2 * rp + 1][2 * q + 1] = dhi;
                s[2 * rp][2 * q + 1]     = xlo;
                s[2 * rp + 1][2 * q]     = xhi;
            }

        // causal mask only on the diagonal tile
        if (kt == qtile) {
#pragma unroll
            for (int i = 0; i < 8; i++)
#pragma unroll
                for (int j = 0; j < 4; j++)
                    if (c0 + j > r0 + i) s[i][j] = -1e30f;
        }

        // online softmax per row (reduce across the 16 tx lanes, same warp)
#pragma unroll
        for (int i = 0; i < 8; i++) {
            float tm = fmaxf(fmaxf(s[i][0], s[i][1]), fmaxf(s[i][2], s[i][3]));
#pragma unroll
            for (int o = 1; o < 16; o <<= 1)
                tm = fmaxf(tm, __shfl_xor_sync(0xffffffffu, tm, o));
            float nm  = fmaxf(m_[i], tm);
            float cor = __expf(m_[i] - nm);
            float rs = 0.f;
#pragma unroll
            for (int j = 0; j < 4; j++) {
                s[i][j] = __expf(s[i][j] - nm);
                rs += s[i][j];
            }
#pragma unroll
            for (int o = 1; o < 16; o <<= 1)
                rs += __shfl_xor_sync(0xffffffffu, rs, o);
            l_[i] = l_[i] * cor + rs;
            m_[i] = nm;
            u64 corp = pk1(cor);
            mul2(acc[i][0], corp);
            mul2(acc[i][1], corp);
        }

        __syncthreads();   // done reading K from KP
        // store P natural: KP[row][key]
#pragma unroll
        for (int i = 0; i < 8; i++) {
            *reinterpret_cast<float4*>(&KP[r0 + i][c0]) =
                make_float4(s[i][0], s[i][1], s[i][2], s[i][3]);
        }
        __syncthreads();

        // ---- acc += P V (V pairs loaded directly as u64, P broadcast) ----
#pragma unroll
        for (int j4 = 0; j4 < 16; j4++) {
            ulonglong2 w0 = *reinterpret_cast<ulonglong2*>(&Vs[j4 * 4 + 0][c0]);
            ulonglong2 w1 = *reinterpret_cast<ulonglong2*>(&Vs[j4 * 4 + 1][c0]);
            ulonglong2 w2 = *reinterpret_cast<ulonglong2*>(&Vs[j4 * 4 + 2][c0]);
            ulonglong2 w3 = *reinterpret_cast<ulonglong2*>(&Vs[j4 * 4 + 3][c0]);
#pragma unroll
            for (int i = 0; i < 8; i++) {
                float4 p = *reinterpret_cast<float4*>(&KP[r0 + i][j4 * 4]);
                u64 px = pk1(p.x), py = pk1(p.y), pz = pk1(p.z), pw = pk1(p.w);
                fma2(acc[i][0], px, w0.x); fma2(acc[i][1], px, w0.y);
                fma2(acc[i][0], py, w1.x); fma2(acc[i][1], py, w1.y);
                fma2(acc[i][0], pz, w2.x); fma2(acc[i][1], pz, w2.y);
                fma2(acc[i][0], pw, w3.x); fma2(acc[i][1], pw, w3.y);
            }
        }
    }

    // write split partials
    const size_t base = (size_t)(b * KSPLIT + split) * TT + q0;
#pragma unroll
    for (int i = 0; i < 8; i++) {
        int r = r0 + i;
        *reinterpret_cast<ulonglong2*>(&g_pacc[(base + r) * HS + c0]) =
            make_ulonglong2(acc[i][0], acc[i][1]);
        if (tx == 0) {
            g_pm[base + r] = m_[i];
            g_pl[base + r] = l_[i];
        }
    }
}

// ---------------------------------------------------------------------------
// Kernel 3: combine split partials into the final output.
// ---------------------------------------------------------------------------
__global__ __launch_bounds__(256) void combine_kernel(float* __restrict__ out) {
    const int idx = blockIdx.x * 256 + threadIdx.x;
    const int d   = idx & (HS - 1);
    const int row = idx >> 6;
    const int b   = row >> 11;
    const int q   = row & (TT - 1);

    float M = -1e30f;
#pragma unroll
    for (int s = 0; s < KSPLIT; s++)
        M = fmaxf(M, g_pm[(size_t)(b * KSPLIT + s) * TT + q]);

    float L = 0.f, A = 0.f;
#pragma unroll
    for (int s = 0; s < KSPLIT; s++) {
        size_t pb = (size_t)(b * KSPLIT + s) * TT + q;
        float w = __expf(g_pm[pb] - M);
        L += g_pl[pb] * w;
        A += g_pacc[pb * HS + d] * w;
    }
    out[idx] = A / L;
}

// ---------------------------------------------------------------------------
extern "C" void kernel_launch(void* const* d_in, const int* in_sizes, int n_in,
                              void* d_out, int out_size) {
    const float* x  = (const float*)d_in[0];
    const float* Wq = (const float*)d_in[1];
    const float* Wk = (const float*)d_in[2];
    const float* Wv = (const float*)d_in[3];
    float* out = (float*)d_out;

    qkv_kernel<<<dim3((BB * TT) / 64, 3, 2), 256>>>(x, Wq, Wk, Wv);
    qkv_add_kernel<<<(3 * BB * TT * HS / 4) / 256, 256>>>();
    attn_partial_kernel<<<dim3(TT / 64, KSPLIT, BB), 128>>>();
    combine_kernel<<<(BB * TT * HS) / 256, 256>>>(out);
}